// round 2
// baseline (speedup 1.0000x reference)
#include <cuda_runtime.h>
#include <math.h>

#define NTOK 4096
#define DDIM 1024
#define SDIM 16
#define NEXP 4
#define HDIM 2048
#define LSEQ 2048
#define BB   2

// ---------------- scratch (static device globals; no allocation) ----------------
__device__ float g_delta[NTOK * DDIM];   // softplus(x@W_delta+b)
__device__ float g_Bm[NTOK * SDIM];
__device__ float g_Cm[NTOK * SDIM];
__device__ float g_ssm[NTOK * DDIM];     // scan output
__device__ float g_moe[NTOK * DDIM];     // accumulated expert output
__device__ float g_G[NTOK * HDIM];       // per-expert hidden (reused across experts)
__device__ int   g_cnt[NEXP];
__device__ int   g_list[NEXP * NTOK];
__device__ float g_wgt[NEXP * NTOK];

// ---------------- helpers ----------------
__device__ __forceinline__ float softplusf(float z) {
    return fmaxf(z, 0.f) + log1pf(__expf(-fabsf(z)));
}

__device__ __forceinline__ float blockReduceSum(float v) {
    __shared__ float sh[9];
    int lane = threadIdx.x & 31, wid = threadIdx.x >> 5;
#pragma unroll
    for (int o = 16; o > 0; o >>= 1) v += __shfl_xor_sync(0xffffffffu, v, o);
    if (lane == 0) sh[wid] = v;
    __syncthreads();
    if (wid == 0) {
        float t = (lane < 8) ? sh[lane] : 0.f;
#pragma unroll
        for (int o = 4; o > 0; o >>= 1) t += __shfl_xor_sync(0xffffffffu, t, o);
        if (lane == 0) sh[8] = t;
    }
    __syncthreads();
    return sh[8];
}

// ---------------- zero moe + counts ----------------
__global__ void k_zero() {
    int i = blockIdx.x * blockDim.x + threadIdx.x;
    int stride = gridDim.x * blockDim.x;
    for (int j = i; j < NTOK * DDIM; j += stride) g_moe[j] = 0.f;
    if (i < NEXP) g_cnt[i] = 0;
}

// ---------------- delta GEMM: softplus(x @ W_delta + b) ----------------
// BM=128, BN=64, BK=16, 256 threads, 8x4 microtile
__global__ void __launch_bounds__(256) k_delta(const float* __restrict__ x,
                                               const float* __restrict__ Wd,
                                               const float* __restrict__ bd) {
    const int K = DDIM, N = DDIM;
    __shared__ float As[16][128];
    __shared__ float Bs[16][64];
    int tid = threadIdx.x;
    int rowBase = blockIdx.x * 128, colBase = blockIdx.y * 64;
    int ar = tid >> 1, ak = (tid & 1) * 8;
    int br = tid >> 4, bc = (tid & 15) * 4;
    int ty = tid >> 4, tx = tid & 15;
    const float* Arow = x + (size_t)(rowBase + ar) * K;
    float acc[8][4] = {};
    for (int k0 = 0; k0 < K; k0 += 16) {
        float4 a0 = *(const float4*)(Arow + k0 + ak);
        float4 a1 = *(const float4*)(Arow + k0 + ak + 4);
        As[ak + 0][ar] = a0.x; As[ak + 1][ar] = a0.y; As[ak + 2][ar] = a0.z; As[ak + 3][ar] = a0.w;
        As[ak + 4][ar] = a1.x; As[ak + 5][ar] = a1.y; As[ak + 6][ar] = a1.z; As[ak + 7][ar] = a1.w;
        *(float4*)&Bs[br][bc] = *(const float4*)(Wd + (size_t)(k0 + br) * N + colBase + bc);
        __syncthreads();
#pragma unroll
        for (int kk = 0; kk < 16; kk++) {
            float4 al = *(const float4*)&As[kk][ty * 8];
            float4 ah = *(const float4*)&As[kk][ty * 8 + 4];
            float4 bv = *(const float4*)&Bs[kk][tx * 4];
            float a[8] = {al.x, al.y, al.z, al.w, ah.x, ah.y, ah.z, ah.w};
            float b[4] = {bv.x, bv.y, bv.z, bv.w};
#pragma unroll
            for (int i = 0; i < 8; i++)
#pragma unroll
                for (int j = 0; j < 4; j++) acc[i][j] = fmaf(a[i], b[j], acc[i][j]);
        }
        __syncthreads();
    }
#pragma unroll
    for (int i = 0; i < 8; i++) {
        int r = rowBase + ty * 8 + i;
#pragma unroll
        for (int j = 0; j < 4; j++) {
            int c = colBase + tx * 4 + j;
            g_delta[(size_t)r * N + c] = softplusf(acc[i][j] + bd[c]);
        }
    }
}

// ---------------- Bm / Cm: skinny GEMM, one warp per token ----------------
__global__ void k_bc(const float* __restrict__ x, const float* __restrict__ WB,
                     const float* __restrict__ WC) {
    int wid = (blockIdx.x * blockDim.x + threadIdx.x) >> 5;
    int lane = threadIdx.x & 31;
    if (wid >= NTOK) return;
    const float* W = (lane < 16) ? WB : WC;
    int col = lane & 15;
    const float* xr = x + (size_t)wid * DDIM;
    float acc = 0.f;
#pragma unroll 8
    for (int k = 0; k < DDIM; k++) acc = fmaf(xr[k], W[k * SDIM + col], acc);
    if (lane < 16) g_Bm[wid * SDIM + col] = acc;
    else           g_Cm[wid * SDIM + col] = acc;
}

// ---------------- selective scan: 16 lanes (states) per (b,d) channel ----------------
__global__ void k_scan(const float* __restrict__ x, const float* __restrict__ A_log,
                       const float* __restrict__ Dp) {
    int tid = threadIdx.x;
    int grp = tid >> 4, s = tid & 15;
    int c = blockIdx.x * 16 + grp;       // channel 0..2047
    int b = c >> 10, d = c & 1023;
    float a = -__expf(A_log[d * SDIM + s]);
    float dpar = Dp[d];
    float h = 0.f;
    const float* xb = x + (size_t)b * LSEQ * DDIM + d;
    const float* db = g_delta + (size_t)b * LSEQ * DDIM + d;
    const float* Bb = g_Bm + (size_t)b * LSEQ * SDIM + s;
    const float* Cb = g_Cm + (size_t)b * LSEQ * SDIM + s;
    float* yb = g_ssm + (size_t)b * LSEQ * DDIM + d;
#pragma unroll 4
    for (int t = 0; t < LSEQ; t++) {
        float dv = db[(size_t)t * DDIM];
        float xv = xb[(size_t)t * DDIM];
        float Bv = Bb[t * SDIM];
        float Cv = Cb[t * SDIM];
        float barA = __expf(fminf(dv * a, 10.f));
        float barB = fminf(fmaxf(dv * Bv, -10.f), 10.f);
        h = fminf(fmaxf(fmaf(barA, h, barB * xv), -10000.f), 10000.f);
        float p = h * Cv;
        p += __shfl_xor_sync(0xffffffffu, p, 8);
        p += __shfl_xor_sync(0xffffffffu, p, 4);
        p += __shfl_xor_sync(0xffffffffu, p, 2);
        p += __shfl_xor_sync(0xffffffffu, p, 1);
        if (s == 0) yb[(size_t)t * DDIM] = p + xv * dpar;
    }
}

// ---------------- router: softmax over E=4, top-2, build per-expert lists ----------------
__global__ void k_router(const float* __restrict__ Wr) {
    int wid = (blockIdx.x * blockDim.x + threadIdx.x) >> 5;
    int lane = threadIdx.x & 31;
    if (wid >= NTOK) return;
    const float* xr = g_ssm + (size_t)wid * DDIM;
    float l[4] = {0.f, 0.f, 0.f, 0.f};
    for (int k = lane; k < DDIM; k += 32) {
        float xv = xr[k];
        float4 w = *(const float4*)(Wr + (size_t)k * 4);
        l[0] = fmaf(xv, w.x, l[0]);
        l[1] = fmaf(xv, w.y, l[1]);
        l[2] = fmaf(xv, w.z, l[2]);
        l[3] = fmaf(xv, w.w, l[3]);
    }
#pragma unroll
    for (int e = 0; e < 4; e++)
#pragma unroll
        for (int o = 16; o > 0; o >>= 1) l[e] += __shfl_xor_sync(0xffffffffu, l[e], o);
    if (lane == 0) {
        float m = fmaxf(fmaxf(l[0], l[1]), fmaxf(l[2], l[3]));
        float p[4]; float ssum = 0.f;
#pragma unroll
        for (int e = 0; e < 4; e++) { p[e] = __expf(l[e] - m); ssum += p[e]; }
#pragma unroll
        for (int e = 0; e < 4; e++) p[e] /= ssum;
        int e1 = 0; float b1 = p[0];
#pragma unroll
        for (int e = 1; e < 4; e++) if (p[e] > b1) { b1 = p[e]; e1 = e; }
        int e2 = -1; float b2 = -1.f;
#pragma unroll
        for (int e = 0; e < 4; e++) if (e != e1 && p[e] > b2) { b2 = p[e]; e2 = e; }
        float wsum = b1 + b2 + 1e-9f;
        float w1 = b1 / wsum, w2 = b2 / wsum;
        int pos1 = atomicAdd(&g_cnt[e1], 1);
        g_list[e1 * NTOK + pos1] = wid; g_wgt[e1 * NTOK + pos1] = w1;
        int pos2 = atomicAdd(&g_cnt[e2], 1);
        g_list[e2 * NTOK + pos2] = wid; g_wgt[e2 * NTOK + pos2] = w2;
    }
}

// ---------------- fused gate+up GEMM (gathered rows): G = silu(X@Wg)*(X@Wu) ----------------
__global__ void __launch_bounds__(256) k_gu(int e, const float* __restrict__ Wg_all,
                                            const float* __restrict__ Wu_all) {
    int cnt = g_cnt[e];
    int rowBase = blockIdx.x * 128;
    if (rowBase >= cnt) return;
    const float* Bg = Wg_all + (size_t)e * DDIM * HDIM;
    const float* Bu = Wu_all + (size_t)e * DDIM * HDIM;
    int colBase = blockIdx.y * 64;
    __shared__ float As[16][128];
    __shared__ float Bgs[16][64];
    __shared__ float Bus[16][64];
    int tid = threadIdx.x;
    int ar = tid >> 1, ak = (tid & 1) * 8;
    int br = tid >> 4, bc = (tid & 15) * 4;
    int ty = tid >> 4, tx = tid & 15;
    int grow = rowBase + ar;
    int srcRow = (grow < cnt) ? g_list[e * NTOK + grow] : g_list[e * NTOK];
    const float* Arow = g_ssm + (size_t)srcRow * DDIM;
    float accg[8][4] = {}, accu[8][4] = {};
    for (int k0 = 0; k0 < DDIM; k0 += 16) {
        float4 a0 = *(const float4*)(Arow + k0 + ak);
        float4 a1 = *(const float4*)(Arow + k0 + ak + 4);
        As[ak + 0][ar] = a0.x; As[ak + 1][ar] = a0.y; As[ak + 2][ar] = a0.z; As[ak + 3][ar] = a0.w;
        As[ak + 4][ar] = a1.x; As[ak + 5][ar] = a1.y; As[ak + 6][ar] = a1.z; As[ak + 7][ar] = a1.w;
        *(float4*)&Bgs[br][bc] = *(const float4*)(Bg + (size_t)(k0 + br) * HDIM + colBase + bc);
        *(float4*)&Bus[br][bc] = *(const float4*)(Bu + (size_t)(k0 + br) * HDIM + colBase + bc);
        __syncthreads();
#pragma unroll
        for (int kk = 0; kk < 16; kk++) {
            float4 al = *(const float4*)&As[kk][ty * 8];
            float4 ah = *(const float4*)&As[kk][ty * 8 + 4];
            float4 bg = *(const float4*)&Bgs[kk][tx * 4];
            float4 bu = *(const float4*)&Bus[kk][tx * 4];
            float a[8] = {al.x, al.y, al.z, al.w, ah.x, ah.y, ah.z, ah.w};
            float bgv[4] = {bg.x, bg.y, bg.z, bg.w};
            float buv[4] = {bu.x, bu.y, bu.z, bu.w};
#pragma unroll
            for (int i = 0; i < 8; i++)
#pragma unroll
                for (int j = 0; j < 4; j++) {
                    accg[i][j] = fmaf(a[i], bgv[j], accg[i][j]);
                    accu[i][j] = fmaf(a[i], buv[j], accu[i][j]);
                }
        }
        __syncthreads();
    }
#pragma unroll
    for (int i = 0; i < 8; i++) {
        int r = rowBase + ty * 8 + i;
        if (r < cnt) {
#pragma unroll
            for (int j = 0; j < 4; j++) {
                int cidx = colBase + tx * 4 + j;
                float gv = accg[i][j];
                float sig = 1.f / (1.f + __expf(-gv));
                g_G[(size_t)r * HDIM + cidx] = gv * sig * accu[i][j];
            }
        }
    }
}

// ---------------- rmsnorm over expert hidden rows ----------------
__global__ void k_rmsg(int e, const float* __restrict__ wn) {
    int m = blockIdx.x;
    if (m >= g_cnt[e]) return;
    float* row = g_G + (size_t)m * HDIM;
    const float* w = wn + (size_t)e * HDIM;
    float v[8]; float ss = 0.f;
#pragma unroll
    for (int i = 0; i < 8; i++) {
        v[i] = row[threadIdx.x + i * 256];
        ss += v[i] * v[i];
    }
    ss = blockReduceSum(ss);
    float inv = 1.f / sqrtf(ss * (1.f / HDIM) + 1e-6f);
#pragma unroll
    for (int i = 0; i < 8; i++)
        row[threadIdx.x + i * 256] = w[threadIdx.x + i * 256] * v[i] * inv;
}

// ---------------- down GEMM + weighted scatter-add into moe ----------------
__global__ void __launch_bounds__(256) k_down(int e, const float* __restrict__ Wd_all) {
    int cnt = g_cnt[e];
    int rowBase = blockIdx.x * 128;
    if (rowBase >= cnt) return;
    const float* Bd = Wd_all + (size_t)e * HDIM * DDIM;
    int colBase = blockIdx.y * 64;
    __shared__ float As[16][128];
    __shared__ float Bs[16][64];
    int tid = threadIdx.x;
    int ar = tid >> 1, ak = (tid & 1) * 8;
    int br = tid >> 4, bc = (tid & 15) * 4;
    int ty = tid >> 4, tx = tid & 15;
    const float* Arow = g_G + (size_t)(rowBase + ar) * HDIM;
    float acc[8][4] = {};
    for (int k0 = 0; k0 < HDIM; k0 += 16) {
        float4 a0 = *(const float4*)(Arow + k0 + ak);
        float4 a1 = *(const float4*)(Arow + k0 + ak + 4);
        As[ak + 0][ar] = a0.x; As[ak + 1][ar] = a0.y; As[ak + 2][ar] = a0.z; As[ak + 3][ar] = a0.w;
        As[ak + 4][ar] = a1.x; As[ak + 5][ar] = a1.y; As[ak + 6][ar] = a1.z; As[ak + 7][ar] = a1.w;
        *(float4*)&Bs[br][bc] = *(const float4*)(Bd + (size_t)(k0 + br) * DDIM + colBase + bc);
        __syncthreads();
#pragma unroll
        for (int kk = 0; kk < 16; kk++) {
            float4 al = *(const float4*)&As[kk][ty * 8];
            float4 ah = *(const float4*)&As[kk][ty * 8 + 4];
            float4 bv = *(const float4*)&Bs[kk][tx * 4];
            float a[8] = {al.x, al.y, al.z, al.w, ah.x, ah.y, ah.z, ah.w};
            float b[4] = {bv.x, bv.y, bv.z, bv.w};
#pragma unroll
            for (int i = 0; i < 8; i++)
#pragma unroll
                for (int j = 0; j < 4; j++) acc[i][j] = fmaf(a[i], b[j], acc[i][j]);
        }
        __syncthreads();
    }
#pragma unroll
    for (int i = 0; i < 8; i++) {
        int r = rowBase + ty * 8 + i;
        if (r < cnt) {
            int tok = g_list[e * NTOK + r];
            float w = g_wgt[e * NTOK + r];
#pragma unroll
            for (int j = 0; j < 4; j++) {
                int cidx = colBase + tx * 4 + j;
                g_moe[(size_t)tok * DDIM + cidx] += w * acc[i][j];
            }
        }
    }
}

// ---------------- final rmsnorm(ssm + moe) ----------------
__global__ void k_final(const float* __restrict__ nw, float* __restrict__ out) {
    int n = blockIdx.x;
    int t = threadIdx.x;
    float v[4]; float ss = 0.f;
#pragma unroll
    for (int i = 0; i < 4; i++) {
        int j = t + i * 256;
        v[i] = g_ssm[(size_t)n * DDIM + j] + g_moe[(size_t)n * DDIM + j];
        ss += v[i] * v[i];
    }
    ss = blockReduceSum(ss);
    float inv = 1.f / sqrtf(ss * (1.f / DDIM) + 1e-6f);
#pragma unroll
    for (int i = 0; i < 4; i++) {
        int j = t + i * 256;
        out[(size_t)n * DDIM + j] = nw[j] * v[i] * inv;
    }
}

// ---------------- launch ----------------
extern "C" void kernel_launch(void* const* d_in, const int* in_sizes, int n_in,
                              void* d_out, int out_size) {
    (void)in_sizes; (void)n_in; (void)out_size;
    const float* x        = (const float*)d_in[0];
    const float* A_log    = (const float*)d_in[1];
    const float* D_param  = (const float*)d_in[2];
    const float* W_delta  = (const float*)d_in[3];
    const float* b_delta  = (const float*)d_in[4];
    const float* W_B      = (const float*)d_in[5];
    const float* W_C      = (const float*)d_in[6];
    const float* W_router = (const float*)d_in[7];
    const float* Wg       = (const float*)d_in[8];
    const float* Wu       = (const float*)d_in[9];
    const float* Wd       = (const float*)d_in[10];
    const float* wn_exp   = (const float*)d_in[11];
    const float* norm_w   = (const float*)d_in[12];
    float* out = (float*)d_out;

    k_zero<<<1024, 256>>>();
    k_delta<<<dim3(32, 16), 256>>>(x, W_delta, b_delta);
    k_bc<<<512, 256>>>(x, W_B, W_C);
    k_scan<<<128, 256>>>(x, A_log, D_param);
    k_router<<<512, 256>>>(W_router);
    for (int e = 0; e < NEXP; e++) {
        k_gu<<<dim3(32, 32), 256>>>(e, Wg, Wu);
        k_rmsg<<<4096, 256>>>(e, wn_exp);
        k_down<<<dim3(32, 16), 256>>>(e, Wd);
    }
    k_final<<<4096, 256>>>(norm_w, out);
}